// round 1
// baseline (speedup 1.0000x reference)
#include <cuda_runtime.h>

#define N_CAP 100000
#define E_CAP 1600000
#define F_DIM 128

// -------- static scratch (allocation-free rule) --------
__device__ float     g_h1[(size_t)N_CAP * F_DIM];   // hop-1 result (51.2 MB)
__device__ float     g_dinv[N_CAP];
__device__ int       g_rowptr[N_CAP + 1];
__device__ int       g_cnt[N_CAP];                  // histogram, then cursor
__device__ int       g_col[E_CAP];                  // CSR col (src) sorted by dst
__device__ int       g_bsums[1024];
__device__ int       g_is64;

// -------- detect edge_index element width (int64 vs int32) --------
__global__ void detect_k(const long long* ei, int E) {
    int is64 = 1;
    int n = E < 128 ? E : 128;
    for (int i = 0; i < n; i++) {
        long long v = ei[i];
        if (v < 0 || v >= (1LL << 31)) { is64 = 0; break; }
    }
    g_is64 = is64;
}

__global__ void zero_cnt_k(int N) {
    int i = blockIdx.x * blockDim.x + threadIdx.x;
    if (i < N) g_cnt[i] = 0;
}

__global__ void hist_k(const void* ei, int E) {
    int e = blockIdx.x * blockDim.x + threadIdx.x;
    if (e >= E) return;
    int dst;
    if (g_is64) dst = (int)((const long long*)ei)[(size_t)E + e];
    else        dst = ((const int*)ei)[(size_t)E + e];
    atomicAdd(&g_cnt[dst], 1);
}

// 3-phase exclusive scan over g_cnt -> g_rowptr (chunks of 1024)
__global__ void scan1_k(int N) {
    __shared__ int sh[256];
    int base = blockIdx.x * 1024;
    int tid  = threadIdx.x;
    int s = 0;
    #pragma unroll
    for (int k = 0; k < 4; k++) {
        int i = base + tid + k * 256;
        if (i < N) s += g_cnt[i];
    }
    sh[tid] = s; __syncthreads();
    for (int off = 128; off > 0; off >>= 1) {
        if (tid < off) sh[tid] += sh[tid + off];
        __syncthreads();
    }
    if (tid == 0) g_bsums[blockIdx.x] = sh[0];
}

__global__ void scan2_k(int NB, int N) {
    int acc = 0;
    for (int b = 0; b < NB; b++) { int v = g_bsums[b]; g_bsums[b] = acc; acc += v; }
    g_rowptr[N] = acc;
}

__global__ void scan3_k(int N) {
    __shared__ int sh[1024];
    int tid = threadIdx.x;
    int i   = blockIdx.x * 1024 + tid;
    int own = (i < N) ? g_cnt[i] : 0;
    sh[tid] = own; __syncthreads();
    for (int off = 1; off < 1024; off <<= 1) {
        int v = (tid >= off) ? sh[tid - off] : 0;
        __syncthreads();
        sh[tid] += v;
        __syncthreads();
    }
    if (i < N) g_rowptr[i] = g_bsums[blockIdx.x] + sh[tid] - own;
}

// dinv = rsqrt(indeg+1); repurpose g_cnt as scatter cursor = rowptr
__global__ void dinv_k(int N) {
    int i = blockIdx.x * blockDim.x + threadIdx.x;
    if (i >= N) return;
    g_dinv[i] = rsqrtf((float)g_cnt[i] + 1.0f);
    g_cnt[i]  = g_rowptr[i];
}

__global__ void scatter_k(const void* ei, int E) {
    int e = blockIdx.x * blockDim.x + threadIdx.x;
    if (e >= E) return;
    int src, dst;
    if (g_is64) {
        src = (int)((const long long*)ei)[e];
        dst = (int)((const long long*)ei)[(size_t)E + e];
    } else {
        src = ((const int*)ei)[e];
        dst = ((const int*)ei)[(size_t)E + e];
    }
    int pos = atomicAdd(&g_cnt[dst], 1);
    g_col[pos] = src;
}

// -------- hop 1: warp per node, float4 per lane --------
__global__ void hop1_k(const float4* __restrict__ x, int N) {
    int gw   = (blockIdx.x * blockDim.x + threadIdx.x) >> 5;
    int lane = threadIdx.x & 31;
    if (gw >= N) return;
    int beg = g_rowptr[gw], end = g_rowptr[gw + 1];
    float4 acc = make_float4(0.f, 0.f, 0.f, 0.f);
    for (int j = beg; j < end; j += 32) {
        int myj = j + lane;
        int s = 0; float w = 0.f;
        if (myj < end) { s = g_col[myj]; w = g_dinv[s]; }
        int cnt = min(32, end - j);
        for (int k = 0; k < cnt; k++) {
            int   ss = __shfl_sync(0xffffffffu, s, k);
            float ww = __shfl_sync(0xffffffffu, w, k);
            float4 v = x[(size_t)ss * 32 + lane];
            acc.x += ww * v.x; acc.y += ww * v.y;
            acc.z += ww * v.z; acc.w += ww * v.w;
        }
    }
    float  di = g_dinv[gw];
    float4 v  = x[(size_t)gw * 32 + lane];
    float  sl = di * di;
    acc.x = di * acc.x + sl * v.x;
    acc.y = di * acc.y + sl * v.y;
    acc.z = di * acc.z + sl * v.z;
    acc.w = di * acc.w + sl * v.w;
    ((float4*)g_h1)[(size_t)gw * 32 + lane] = acc;
}

// -------- hop 2 fused with linear: out[n,c] = h2[n,:] . W[c,:] + b[c] --------
__global__ void hop2_gemm_k(const float* __restrict__ W, const float* __restrict__ b,
                            float* __restrict__ out, int N, int C) {
    extern __shared__ float sm[];               // C*F + C floats
    float4* sW4 = (float4*)sm;
    float*  sb  = sm + C * F_DIM;
    for (int idx = threadIdx.x; idx < C * F_DIM; idx += blockDim.x) sm[idx] = W[idx];
    for (int idx = threadIdx.x; idx < C; idx += blockDim.x) sb[idx] = b[idx];
    __syncthreads();

    int gw   = (blockIdx.x * blockDim.x + threadIdx.x) >> 5;
    int lane = threadIdx.x & 31;
    if (gw >= N) return;

    const float4* h = (const float4*)g_h1;
    int beg = g_rowptr[gw], end = g_rowptr[gw + 1];
    float4 acc = make_float4(0.f, 0.f, 0.f, 0.f);
    for (int j = beg; j < end; j += 32) {
        int myj = j + lane;
        int s = 0; float w = 0.f;
        if (myj < end) { s = g_col[myj]; w = g_dinv[s]; }
        int cnt = min(32, end - j);
        for (int k = 0; k < cnt; k++) {
            int   ss = __shfl_sync(0xffffffffu, s, k);
            float ww = __shfl_sync(0xffffffffu, w, k);
            float4 v = h[(size_t)ss * 32 + lane];
            acc.x += ww * v.x; acc.y += ww * v.y;
            acc.z += ww * v.z; acc.w += ww * v.w;
        }
    }
    float  di = g_dinv[gw];
    float4 v  = h[(size_t)gw * 32 + lane];
    float  sl = di * di;
    acc.x = di * acc.x + sl * v.x;
    acc.y = di * acc.y + sl * v.y;
    acc.z = di * acc.z + sl * v.z;
    acc.w = di * acc.w + sl * v.w;

    // acc = h2 row segment [lane*4 .. lane*4+3]; project onto W rows
    for (int c = 0; c < C; c++) {
        float4 wv = sW4[c * 32 + lane];
        float p = acc.x * wv.x + acc.y * wv.y + acc.z * wv.z + acc.w * wv.w;
        p += __shfl_xor_sync(0xffffffffu, p, 16);
        p += __shfl_xor_sync(0xffffffffu, p, 8);
        p += __shfl_xor_sync(0xffffffffu, p, 4);
        p += __shfl_xor_sync(0xffffffffu, p, 2);
        p += __shfl_xor_sync(0xffffffffu, p, 1);
        if (lane == (c & 31)) out[(size_t)gw * C + c] = p + sb[c];
    }
}

extern "C" void kernel_launch(void* const* d_in, const int* in_sizes, int n_in,
                              void* d_out, int out_size) {
    const float* x  = (const float*)d_in[0];
    const void*  ei = d_in[1];
    const float* W  = (const float*)d_in[2];
    const float* b  = (const float*)d_in[3];

    int C = in_sizes[3];                 // 40
    int F = in_sizes[2] / C;             // 128
    int N = in_sizes[0] / F;             // 100000
    int E = in_sizes[1] / 2;             // 1600000
    int NB = (N + 1023) / 1024;

    detect_k<<<1, 1>>>((const long long*)ei, E);
    zero_cnt_k<<<(N + 255) / 256, 256>>>(N);
    hist_k<<<(E + 255) / 256, 256>>>(ei, E);
    scan1_k<<<NB, 256>>>(N);
    scan2_k<<<1, 1>>>(NB, N);
    scan3_k<<<NB, 1024>>>(N);
    dinv_k<<<(N + 255) / 256, 256>>>(N);
    scatter_k<<<(E + 255) / 256, 256>>>(ei, E);

    int tpb = 256;
    int blocks = (N * 32 + tpb - 1) / tpb;   // warp per node
    hop1_k<<<blocks, tpb>>>((const float4*)x, N);
    size_t shmem = (size_t)(C * F + C) * sizeof(float);
    hop2_gemm_k<<<blocks, tpb, shmem>>>(W, b, (float*)d_out, N, C);
}